// round 1
// baseline (speedup 1.0000x reference)
#include <cuda_runtime.h>

#define NN 100000
#define NE 1600000
#define DH 128

typedef unsigned long long u64;

// ---------------- scratch (device globals: no allocation allowed) -----------
__device__ int   g_deg[NN];
__device__ int   g_rowoff[NN + 1];
__device__ int   g_cursor[NN];
__device__ int   g_blocksum[512];
__device__ int   g_blockoff[512];
__device__ int   g_csr_src[NE];
__device__ float g_agg[(size_t)NN * DH];
__device__ float g_h1 [(size_t)NN * DH];
__device__ float g_h2 [(size_t)NN * DH];

// ---------------- CSR build --------------------------------------------------
__global__ void k_zero_deg() {
    int i = blockIdx.x * blockDim.x + threadIdx.x;
    if (i < NN) g_deg[i] = 0;
}

__global__ void k_count(const int* __restrict__ dst) {
    int e = blockIdx.x * blockDim.x + threadIdx.x;
    if (e < NE) atomicAdd(&g_deg[dst[e]], 1);
}

__global__ void k_scan_block() {
    __shared__ int s[256];
    int t = threadIdx.x;
    int i = blockIdx.x * 256 + t;
    int v = (i < NN) ? g_deg[i] : 0;
    s[t] = v; __syncthreads();
#pragma unroll
    for (int off = 1; off < 256; off <<= 1) {
        int tv = (t >= off) ? s[t - off] : 0;
        __syncthreads();
        s[t] += tv;
        __syncthreads();
    }
    if (i < NN) g_rowoff[i] = s[t] - v;      // block-local exclusive
    if (t == 255) g_blocksum[blockIdx.x] = s[255];
}

__global__ void k_scan_top(int nblocks) {
    __shared__ int s[512];
    int t = threadIdx.x;
    int v = (t < nblocks) ? g_blocksum[t] : 0;
    s[t] = v; __syncthreads();
    for (int off = 1; off < 512; off <<= 1) {
        int tv = (t >= off) ? s[t - off] : 0;
        __syncthreads();
        s[t] += tv;
        __syncthreads();
    }
    if (t < nblocks) g_blockoff[t] = s[t] - v;
}

__global__ void k_scan_add() {
    int i = blockIdx.x * 256 + threadIdx.x;
    if (i < NN) {
        int r = g_rowoff[i] + g_blockoff[blockIdx.x];
        g_rowoff[i] = r;
        g_cursor[i] = r;
    }
    if (i == 0) g_rowoff[NN] = NE;
}

__global__ void k_scatter(const int* __restrict__ src, const int* __restrict__ dst) {
    int e = blockIdx.x * blockDim.x + threadIdx.x;
    if (e < NE) {
        int p = atomicAdd(&g_cursor[dst[e]], 1);
        g_csr_src[p] = src[e];
    }
}

// ---------------- mean aggregation: one warp per destination node -----------
__global__ void k_agg(const float* __restrict__ feat, float* __restrict__ out) {
    int w    = (blockIdx.x * blockDim.x + threadIdx.x) >> 5;
    int lane = threadIdx.x & 31;
    if (w >= NN) return;
    int beg = g_rowoff[w], end = g_rowoff[w + 1];
    float ax = 0.f, ay = 0.f, az = 0.f, aw = 0.f;
    int e = beg;
    for (; e + 2 <= end; e += 2) {               // unroll 2 -> MLP=2 on the gather
        int s0 = g_csr_src[e], s1 = g_csr_src[e + 1];
        float4 v0 = *(const float4*)(feat + (size_t)s0 * DH + lane * 4);
        float4 v1 = *(const float4*)(feat + (size_t)s1 * DH + lane * 4);
        ax += v0.x + v1.x; ay += v0.y + v1.y;
        az += v0.z + v1.z; aw += v0.w + v1.w;
    }
    if (e < end) {
        int s0 = g_csr_src[e];
        float4 v0 = *(const float4*)(feat + (size_t)s0 * DH + lane * 4);
        ax += v0.x; ay += v0.y; az += v0.z; aw += v0.w;
    }
    int deg = end - beg;
    float inv = 1.0f / (float)(deg > 1 ? deg : 1);
    float4 r = make_float4(ax * inv, ay * inv, az * inv, aw * inv);
    *(float4*)(out + (size_t)w * DH + lane * 4) = r;
}

// ---------------- fused dual GEMM: relu(agg@Wn + hin@Wr + b) ----------------
// BM=128, BN=128(=H), BK=16, 256 threads, each computes 8x8 via packed f32x2 FMA.
__global__ __launch_bounds__(256) void k_gemm(
    const float* __restrict__ Aagg, const float* __restrict__ Hin,
    const float* __restrict__ Wn,   const float* __restrict__ Wr,
    const float* __restrict__ bias, float* __restrict__ Hout)
{
    __shared__ float As[16][132];   // [k][row], pad 132 keeps 16B align, shifts banks
    __shared__ float Ws[16][132];   // [k][col]
    const int tid = threadIdx.x;
    const int ty = tid >> 4, tx = tid & 15;
    const int row0 = ty * 8, col0 = tx * 8;
    const int blockRow = blockIdx.x * 128;

    u64 acc[8][4];
#pragma unroll
    for (int i = 0; i < 8; i++)
#pragma unroll
        for (int j = 0; j < 4; j++) acc[i][j] = 0ull;   // packed (0.f,0.f)

#pragma unroll
    for (int half = 0; half < 2; half++) {
        const float* src  = half ? Hin : Aagg;
        const float* wsrc = half ? Wr  : Wn;
        for (int kt = 0; kt < 128; kt += 16) {
            __syncthreads();
            // A tile -> As[k][row]
#pragma unroll
            for (int l = 0; l < 2; l++) {
                int idx = tid + l * 256;          // 0..511
                int r = idx >> 2, kq = idx & 3;
                int grow = blockRow + r;
                float4 v = make_float4(0.f, 0.f, 0.f, 0.f);
                if (grow < NN)
                    v = *(const float4*)(src + (size_t)grow * DH + kt + kq * 4);
                As[kq * 4 + 0][r] = v.x; As[kq * 4 + 1][r] = v.y;
                As[kq * 4 + 2][r] = v.z; As[kq * 4 + 3][r] = v.w;
            }
            // W tile -> Ws[k][col]
#pragma unroll
            for (int l = 0; l < 2; l++) {
                int idx = tid + l * 256;
                int r = idx >> 5, c = (idx & 31) * 4;
                *(float4*)&Ws[r][c] = *(const float4*)(wsrc + (size_t)(kt + r) * DH + c);
            }
            __syncthreads();
#pragma unroll
            for (int kk = 0; kk < 16; kk++) {
                float4 a0 = *(const float4*)&As[kk][row0];
                float4 a1 = *(const float4*)&As[kk][row0 + 4];
                float a[8] = {a0.x, a0.y, a0.z, a0.w, a1.x, a1.y, a1.z, a1.w};
                u64 b2[4];
#pragma unroll
                for (int j = 0; j < 4; j++)
                    b2[j] = *(const u64*)&Ws[kk][col0 + j * 2];
#pragma unroll
                for (int i = 0; i < 8; i++) {
                    unsigned ai = __float_as_uint(a[i]);
                    u64 av;
                    asm("mov.b64 %0, {%1, %1};" : "=l"(av) : "r"(ai));
#pragma unroll
                    for (int j = 0; j < 4; j++)
                        asm("fma.rn.f32x2 %0, %1, %2, %0;"
                            : "+l"(acc[i][j]) : "l"(av), "l"(b2[j]));
                }
            }
        }
    }
    // epilogue: unpack, +bias, relu, store
    float bv[8];
    {
        float4 t0 = *(const float4*)(bias + col0);
        float4 t1 = *(const float4*)(bias + col0 + 4);
        bv[0]=t0.x; bv[1]=t0.y; bv[2]=t0.z; bv[3]=t0.w;
        bv[4]=t1.x; bv[5]=t1.y; bv[6]=t1.z; bv[7]=t1.w;
    }
#pragma unroll
    for (int i = 0; i < 8; i++) {
        int grow = blockRow + row0 + i;
        if (grow >= NN) continue;
        float c[8];
#pragma unroll
        for (int j = 0; j < 4; j++) {
            unsigned lo, hi;
            asm("mov.b64 {%0, %1}, %2;" : "=r"(lo), "=r"(hi) : "l"(acc[i][j]));
            c[j * 2]     = __uint_as_float(lo);
            c[j * 2 + 1] = __uint_as_float(hi);
        }
#pragma unroll
        for (int j = 0; j < 8; j++) c[j] = fmaxf(c[j] + bv[j], 0.0f);
        float4 o0 = make_float4(c[0], c[1], c[2], c[3]);
        float4 o1 = make_float4(c[4], c[5], c[6], c[7]);
        *(float4*)(Hout + (size_t)grow * DH + col0)     = o0;
        *(float4*)(Hout + (size_t)grow * DH + col0 + 4) = o1;
    }
}

// ---------------- head: logits = h2 @ Wh + bh, one warp per node ------------
__global__ void k_head(const float* __restrict__ h2, const float* __restrict__ Wh,
                       const float* __restrict__ bh, float* __restrict__ out) {
    int w    = (blockIdx.x * blockDim.x + threadIdx.x) >> 5;
    int lane = threadIdx.x & 31;
    if (w >= NN) return;
    float4 v  = *(const float4*)(h2 + (size_t)w * DH + lane * 4);
    float4 wt = *(const float4*)(Wh + lane * 4);
    float s = v.x * wt.x + v.y * wt.y + v.z * wt.z + v.w * wt.w;
#pragma unroll
    for (int off = 16; off; off >>= 1) s += __shfl_xor_sync(0xFFFFFFFFu, s, off);
    if (lane == 0) out[w] = s + bh[0];
}

// ---------------- launch -----------------------------------------------------
extern "C" void kernel_launch(void* const* d_in, const int* in_sizes, int n_in,
                              void* d_out, int out_size) {
    const float* x   = (const float*)d_in[0];
    const int*   ei  = (const int*)  d_in[1];
    const int*   src = ei;          // edge_index[0]
    const int*   dst = ei + NE;     // edge_index[1]
    const float* Wn0 = (const float*)d_in[2];
    const float* Wr0 = (const float*)d_in[3];
    const float* b0  = (const float*)d_in[4];
    const float* Wn1 = (const float*)d_in[5];
    const float* Wr1 = (const float*)d_in[6];
    const float* b1  = (const float*)d_in[7];
    const float* Wh  = (const float*)d_in[8];
    const float* bh  = (const float*)d_in[9];
    float* out = (float*)d_out;

    float *agg, *h1, *h2;
    cudaGetSymbolAddress((void**)&agg, g_agg);
    cudaGetSymbolAddress((void**)&h1,  g_h1);
    cudaGetSymbolAddress((void**)&h2,  g_h2);

    const int NB_N  = (NN + 255) / 256;   // 391
    const int NB_E  = (NE + 255) / 256;   // 6250
    const int NB_W  = (NN * 32 + 255) / 256;  // 12500 (warp per node)
    const int NB_G  = (NN + 127) / 128;   // 782

    // CSR build (graph is the same both layers)
    k_zero_deg  <<<NB_N, 256>>>();
    k_count     <<<NB_E, 256>>>(dst);
    k_scan_block<<<NB_N, 256>>>();
    k_scan_top  <<<1,   512>>>(NB_N);
    k_scan_add  <<<NB_N, 256>>>();
    k_scatter   <<<NB_E, 256>>>(src, dst);

    // layer 0
    k_agg <<<NB_W, 256>>>(x, agg);
    k_gemm<<<NB_G, 256>>>(agg, x, Wn0, Wr0, b0, h1);
    // layer 1
    k_agg <<<NB_W, 256>>>(h1, agg);
    k_gemm<<<NB_G, 256>>>(agg, h1, Wn1, Wr1, b1, h2);
    // head
    k_head<<<NB_W, 256>>>(h2, Wh, bh, out);
}

// round 3
// speedup vs baseline: 1.4386x; 1.4386x over previous
#include <cuda_runtime.h>
#include <cuda_bf16.h>
#include <cstdint>

#define NN 100000
#define NE 1600000
#define DH 128
#define NTILES ((NN + 127) / 128)
#define SB 40   // padded smem row stride (bf16 elems): 80B -> conflict-free ldmatrix

typedef unsigned int u32;
typedef unsigned short u16;

// ---------------- scratch (device globals: no allocation allowed) -----------
__device__ int   g_deg[NN];
__device__ int   g_rowoff[NN + 1];
__device__ int   g_cursor[NN];
__device__ int   g_blocksum[512];
__device__ int   g_blockoff[512];
__device__ int   g_csr_src[NE];
__device__ float g_agg[(size_t)NN * DH];
__device__ float g_h1 [(size_t)NN * DH];
__device__ float g_h2 [(size_t)NN * DH];
// 8 weight images, [n][k] row-major 128x128 bf16: (Wn0,Wr0,Wn1,Wr1) x (hi,lo)
__device__ u16 g_wimg[8][16384];

__device__ __forceinline__ u32 smem_u32(const void* p) {
    u32 a;
    asm("{ .reg .u64 t; cvta.to.shared.u64 t, %1; cvt.u32.u64 %0, t; }"
        : "=r"(a) : "l"(p));
    return a;
}

// ---------------- CSR build --------------------------------------------------
__global__ void k_zero_deg() {
    int i = blockIdx.x * blockDim.x + threadIdx.x;
    if (i < NN) g_deg[i] = 0;
}
__global__ void k_count(const int* __restrict__ dst) {
    int e = blockIdx.x * blockDim.x + threadIdx.x;
    if (e < NE) atomicAdd(&g_deg[dst[e]], 1);
}
__global__ void k_scan_block() {
    __shared__ int s[256];
    int t = threadIdx.x;
    int i = blockIdx.x * 256 + t;
    int v = (i < NN) ? g_deg[i] : 0;
    s[t] = v; __syncthreads();
#pragma unroll
    for (int off = 1; off < 256; off <<= 1) {
        int tv = (t >= off) ? s[t - off] : 0;
        __syncthreads();
        s[t] += tv;
        __syncthreads();
    }
    if (i < NN) g_rowoff[i] = s[t] - v;
    if (t == 255) g_blocksum[blockIdx.x] = s[255];
}
__global__ void k_scan_top(int nblocks) {
    __shared__ int s[512];
    int t = threadIdx.x;
    int v = (t < nblocks) ? g_blocksum[t] : 0;
    s[t] = v; __syncthreads();
    for (int off = 1; off < 512; off <<= 1) {
        int tv = (t >= off) ? s[t - off] : 0;
        __syncthreads();
        s[t] += tv;
        __syncthreads();
    }
    if (t < nblocks) g_blockoff[t] = s[t] - v;
}
__global__ void k_scan_add() {
    int i = blockIdx.x * 256 + threadIdx.x;
    if (i < NN) {
        int r = g_rowoff[i] + g_blockoff[blockIdx.x];
        g_rowoff[i] = r;
        g_cursor[i] = r;
    }
    if (i == 0) g_rowoff[NN] = NE;
}
__global__ void k_scatter(const int* __restrict__ src, const int* __restrict__ dst) {
    int e = blockIdx.x * blockDim.x + threadIdx.x;
    if (e < NE) {
        int p = atomicAdd(&g_cursor[dst[e]], 1);
        g_csr_src[p] = src[e];
    }
}

// ---------------- mean aggregation: one warp per destination node -----------
__global__ void k_agg(const float* __restrict__ feat, float* __restrict__ out) {
    int w    = (blockIdx.x * blockDim.x + threadIdx.x) >> 5;
    int lane = threadIdx.x & 31;
    if (w >= NN) return;
    int beg = g_rowoff[w], end = g_rowoff[w + 1];
    float ax = 0.f, ay = 0.f, az = 0.f, aw = 0.f;
    int e = beg;
    for (; e + 4 <= end; e += 4) {                 // MLP = 4 on the gather
        int s0 = g_csr_src[e],     s1 = g_csr_src[e + 1];
        int s2 = g_csr_src[e + 2], s3 = g_csr_src[e + 3];
        float4 v0 = *(const float4*)(feat + (size_t)s0 * DH + lane * 4);
        float4 v1 = *(const float4*)(feat + (size_t)s1 * DH + lane * 4);
        float4 v2 = *(const float4*)(feat + (size_t)s2 * DH + lane * 4);
        float4 v3 = *(const float4*)(feat + (size_t)s3 * DH + lane * 4);
        ax += (v0.x + v1.x) + (v2.x + v3.x);
        ay += (v0.y + v1.y) + (v2.y + v3.y);
        az += (v0.z + v1.z) + (v2.z + v3.z);
        aw += (v0.w + v1.w) + (v2.w + v3.w);
    }
    for (; e < end; e++) {
        int s0 = g_csr_src[e];
        float4 v0 = *(const float4*)(feat + (size_t)s0 * DH + lane * 4);
        ax += v0.x; ay += v0.y; az += v0.z; aw += v0.w;
    }
    int deg = end - beg;
    float inv = 1.0f / (float)(deg > 1 ? deg : 1);
    float4 r = make_float4(ax * inv, ay * inv, az * inv, aw * inv);
    *(float4*)(out + (size_t)w * DH + lane * 4) = r;
}

// ---------------- weight prep: transpose + bf16 hi/lo split -----------------
__global__ void k_prep_w(const float* __restrict__ Wn0, const float* __restrict__ Wr0,
                         const float* __restrict__ Wn1, const float* __restrict__ Wr1) {
    int idx = blockIdx.x * blockDim.x + threadIdx.x;   // 0..65535
    int mat = idx >> 14;
    int e   = idx & 16383;
    int n = e >> 7, k = e & 127;
    const float* W = (mat == 0) ? Wn0 : (mat == 1) ? Wr0 : (mat == 2) ? Wn1 : Wr1;
    float v = W[k * 128 + n];                          // B[n][k] = W[k][n]
    __nv_bfloat16 hi = __float2bfloat16(v);
    float lof = v - __bfloat162float(hi);
    __nv_bfloat16 lo = __float2bfloat16(lof);
    g_wimg[2 * mat][n * 128 + k]     = __bfloat16_as_ushort(hi);
    g_wimg[2 * mat + 1][n * 128 + k] = __bfloat16_as_ushort(lo);
}

// ---------------- tensor-core fused dual GEMM (mma.sync, 3xBF16) ------------
// Hout = relu( Aagg @ Wn + Hin @ Wr + bias )
__device__ __forceinline__ void ldm_x4(u32& r0, u32& r1, u32& r2, u32& r3, u32 addr) {
    asm volatile("ldmatrix.sync.aligned.m8n8.x4.shared.b16 {%0,%1,%2,%3}, [%4];"
                 : "=r"(r0), "=r"(r1), "=r"(r2), "=r"(r3) : "r"(addr));
}
__device__ __forceinline__ void mma16816(float* c, const u32* a, u32 b0, u32 b1) {
    asm volatile(
        "mma.sync.aligned.m16n8k16.row.col.f32.bf16.bf16.f32 "
        "{%0,%1,%2,%3},{%4,%5,%6,%7},{%8,%9},{%0,%1,%2,%3};"
        : "+f"(c[0]), "+f"(c[1]), "+f"(c[2]), "+f"(c[3])
        : "r"(a[0]), "r"(a[1]), "r"(a[2]), "r"(a[3]), "r"(b0), "r"(b1));
}

__global__ __launch_bounds__(256, 2)
void k_gemm_mma(const float* __restrict__ Aagg, const float* __restrict__ Hin,
                const u16* __restrict__ BnH, const u16* __restrict__ BnL,
                const u16* __restrict__ BrH, const u16* __restrict__ BrL,
                const float* __restrict__ bias, float* __restrict__ Hout)
{
    __shared__ u16 AsH[128 * SB], AsL[128 * SB], BsH[128 * SB], BsL[128 * SB];
    const int tid = threadIdx.x, wid = tid >> 5, lane = tid & 31;
    const int blockRow = blockIdx.x * 128;
    const int warpR = (wid & 3) * 32;     // 4 M-warps
    const int warpC = (wid >> 2) * 64;    // 2 N-warps

    const u32 ah_b = smem_u32(AsH), al_b = smem_u32(AsL);
    const u32 bh_b = smem_u32(BsH), bl_b = smem_u32(BsL);

    float acc[2][8][4];
#pragma unroll
    for (int i = 0; i < 2; i++)
#pragma unroll
        for (int j = 0; j < 8; j++)
#pragma unroll
            for (int q = 0; q < 4; q++) acc[i][j][q] = 0.f;

    // A-convert indexing: row = tid>>1 (0..127), col half = (tid&1)*16
    const int arow = tid >> 1, acol = (tid & 1) * 16;
    const int agrow = blockRow + arow;

#pragma unroll
    for (int half = 0; half < 2; half++) {
        const float* src = half ? Hin : Aagg;
        const u16* WH = half ? BrH : BnH;
        const u16* WL = half ? BrL : BnL;

        for (int kc = 0; kc < 4; kc++) {
            __syncthreads();   // previous chunk fully consumed
            // ---- A: fp32 -> bf16 hi/lo into padded smem tiles ----
            {
                const float* rp = src + (size_t)agrow * DH + kc * 32 + acol;
#pragma unroll
                for (int c = 0; c < 4; c++) {
                    float4 v = (agrow < NN) ? *(const float4*)(rp + c * 4)
                                            : make_float4(0.f, 0.f, 0.f, 0.f);
                    __nv_bfloat16 h0 = __float2bfloat16(v.x);
                    __nv_bfloat16 h1 = __float2bfloat16(v.y);
                    __nv_bfloat16 h2 = __float2bfloat16(v.z);
                    __nv_bfloat16 h3 = __float2bfloat16(v.w);
                    __nv_bfloat16 l0 = __float2bfloat16(v.x - __bfloat162float(h0));
                    __nv_bfloat16 l1 = __float2bfloat16(v.y - __bfloat162float(h1));
                    __nv_bfloat16 l2 = __float2bfloat16(v.z - __bfloat162float(h2));
                    __nv_bfloat16 l3 = __float2bfloat16(v.w - __bfloat162float(h3));
                    uint2 ph, pl;
                    ph.x = (u32)__bfloat16_as_ushort(h0) | ((u32)__bfloat16_as_ushort(h1) << 16);
                    ph.y = (u32)__bfloat16_as_ushort(h2) | ((u32)__bfloat16_as_ushort(h3) << 16);
                    pl.x = (u32)__bfloat16_as_ushort(l0) | ((u32)__bfloat16_as_ushort(l1) << 16);
                    pl.y = (u32)__bfloat16_as_ushort(l2) | ((u32)__bfloat16_as_ushort(l3) << 16);
                    int off = arow * SB + acol + c * 4;
                    *(uint2*)&AsH[off] = ph;
                    *(uint2*)&AsL[off] = pl;
                }
            }
            // ---- B: copy k-chunk of the hi/lo weight images ----
            {
#pragma unroll
                for (int i = 0; i < 4; i++) {
                    int p = tid + i * 256;          // 0..1023
                    int img = p >> 9;               // 0 = hi, 1 = lo
                    int idx = p & 511;
                    int n = idx >> 2, part = idx & 3;
                    const u16* s = (img ? WL : WH) + n * 128 + kc * 32 + part * 8;
                    u16* d = (img ? BsL : BsH) + n * SB + part * 8;
                    *(uint4*)d = *(const uint4*)s;
                }
            }
            __syncthreads();

            // ---- compute: 3 passes x 2 k-steps x 16 mma ----
#pragma unroll
            for (int p = 0; p < 3; p++) {
                u32 a_base = (p == 2) ? al_b : ah_b;
                u32 b_base = (p == 1) ? bl_b : bh_b;
#pragma unroll
                for (int ks = 0; ks < 2; ks++) {
                    int k0 = ks * 16;
                    u32 afrag[2][4];
#pragma unroll
                    for (int mi = 0; mi < 2; mi++) {
                        int rowA = warpR + mi * 16 + (lane & 15);
                        int colA = k0 + ((lane >> 4) << 3);
                        ldm_x4(afrag[mi][0], afrag[mi][1], afrag[mi][2], afrag[mi][3],
                               a_base + (u32)(rowA * SB + colA) * 2);
                    }
                    u32 bfrag[4][4];
#pragma unroll
                    for (int pj = 0; pj < 4; pj++) {
                        int nB = warpC + pj * 16 + ((lane >> 4) << 3) + (lane & 7);
                        int kB = k0 + (lane & 8);
                        ldm_x4(bfrag[pj][0], bfrag[pj][1], bfrag[pj][2], bfrag[pj][3],
                               b_base + (u32)(nB * SB + kB) * 2);
                    }
#pragma unroll
                    for (int mi = 0; mi < 2; mi++)
#pragma unroll
                        for (int nj = 0; nj < 8; nj++) {
                            const u32* bp = bfrag[nj >> 1];
                            u32 b0 = (nj & 1) ? bp[2] : bp[0];
                            u32 b1 = (nj & 1) ? bp[3] : bp[1];
                            mma16816(acc[mi][nj], afrag[mi], b0, b1);
                        }
                }
            }
        }
    }

    // ---- epilogue: bias + relu + store ----
    const int g = lane >> 2, tg = lane & 3;
#pragma unroll
    for (int mi = 0; mi < 2; mi++) {
        int row0 = blockRow + warpR + mi * 16 + g;
        int row1 = row0 + 8;
#pragma unroll
        for (int nj = 0; nj < 8; nj++) {
            int col = warpC + nj * 8 + tg * 2;
            float b0v = bias[col], b1v = bias[col + 1];
            if (row0 < NN) {
                float2 o;
                o.x = fmaxf(acc[mi][nj][0] + b0v, 0.f);
                o.y = fmaxf(acc[mi][nj][1] + b1v, 0.f);
                *(float2*)(Hout + (size_t)row0 * DH + col) = o;
            }
            if (row1 < NN) {
                float2 o;
                o.x = fmaxf(acc[mi][nj][2] + b0v, 0.f);
                o.y = fmaxf(acc[mi][nj][3] + b1v, 0.f);
                *(float2*)(Hout + (size_t)row1 * DH + col) = o;
            }
        }
    }
}

// ---------------- head: logits = h2 @ Wh + bh, one warp per node ------------
__global__ void k_head(const float* __restrict__ h2, const float* __restrict__ Wh,
                       const float* __restrict__ bh, float* __restrict__ out) {
    int w    = (blockIdx.x * blockDim.x + threadIdx.x) >> 5;
    int lane = threadIdx.x & 31;
    if (w >= NN) return;
    float4 v  = *(const float4*)(h2 + (size_t)w * DH + lane * 4);
    float4 wt = *(const float4*)(Wh + lane * 4);
    float s = v.x * wt.x + v.y * wt.y + v.z * wt.z + v.w * wt.w;
#pragma unroll
    for (int off = 16; off; off >>= 1) s += __shfl_xor_sync(0xFFFFFFFFu, s, off);
    if (lane == 0) out[w] = s + bh[0];
}

// ---------------- launch -----------------------------------------------------
extern "C" void kernel_launch(void* const* d_in, const int* in_sizes, int n_in,
                              void* d_out, int out_size) {
    const float* x   = (const float*)d_in[0];
    const int*   ei  = (const int*)  d_in[1];
    const int*   src = ei;
    const int*   dst = ei + NE;
    const float* Wn0 = (const float*)d_in[2];
    const float* Wr0 = (const float*)d_in[3];
    const float* b0  = (const float*)d_in[4];
    const float* Wn1 = (const float*)d_in[5];
    const float* Wr1 = (const float*)d_in[6];
    const float* b1  = (const float*)d_in[7];
    const float* Wh  = (const float*)d_in[8];
    const float* bh  = (const float*)d_in[9];
    float* out = (float*)d_out;

    float *agg, *h1, *h2;
    u16* wimg;
    cudaGetSymbolAddress((void**)&agg,  g_agg);
    cudaGetSymbolAddress((void**)&h1,   g_h1);
    cudaGetSymbolAddress((void**)&h2,   g_h2);
    cudaGetSymbolAddress((void**)&wimg, g_wimg);

    const int NB_N = (NN + 255) / 256;
    const int NB_E = (NE + 255) / 256;
    const int NB_W = (NN * 32 + 255) / 256;

    // CSR build
    k_zero_deg  <<<NB_N, 256>>>();
    k_count     <<<NB_E, 256>>>(dst);
    k_scan_block<<<NB_N, 256>>>();
    k_scan_top  <<<1,   512>>>(NB_N);
    k_scan_add  <<<NB_N, 256>>>();
    k_scatter   <<<NB_E, 256>>>(src, dst);

    // weight prep
    k_prep_w<<<256, 256>>>(Wn0, Wr0, Wn1, Wr1);

    // layer 0
    k_agg     <<<NB_W, 256>>>(x, agg);
    k_gemm_mma<<<NTILES, 256>>>(agg, x,
        wimg + 0 * 16384, wimg + 1 * 16384, wimg + 2 * 16384, wimg + 3 * 16384, b0, h1);
    // layer 1
    k_agg     <<<NB_W, 256>>>(h1, agg);
    k_gemm_mma<<<NTILES, 256>>>(agg, h1,
        wimg + 4 * 16384, wimg + 5 * 16384, wimg + 6 * 16384, wimg + 7 * 16384, b1, h2);
    // head
    k_head<<<NB_W, 256>>>(h2, Wh, bh, out);
}

// round 4
// speedup vs baseline: 1.5962x; 1.1096x over previous
#include <cuda_runtime.h>
#include <cuda_bf16.h>
#include <cuda_fp16.h>
#include <cstdint>

#define NN 100000
#define NE 1600000
#define DH 128
#define NTILES ((NN + 127) / 128)
#define SB 40   // padded smem row stride (bf16 elems): 80B -> conflict-free ldmatrix

typedef unsigned int u32;
typedef unsigned short u16;

// ---------------- scratch (device globals: no allocation allowed) -----------
__device__ int    g_deg[NN];
__device__ int    g_rowoff[NN + 1];
__device__ int    g_cursor[NN];
__device__ int    g_blocksum[512];
__device__ int    g_blockoff[512];
__device__ int    g_csr_src[NE];
__device__ float  g_agg[(size_t)NN * DH];
__device__ float  g_h1 [(size_t)NN * DH];
__device__ __half g_xh [(size_t)NN * DH];   // fp16 copy of x   (gather input L0)
__device__ __half g_h1h[(size_t)NN * DH];   // fp16 copy of h1  (gather input L1)
// 8 weight images, [n][k] row-major 128x128 bf16: (Wn0,Wr0,Wn1,Wr1) x (hi,lo)
__device__ u16 g_wimg[8][16384];

__device__ __forceinline__ u32 smem_u32(const void* p) {
    u32 a;
    asm("{ .reg .u64 t; cvta.to.shared.u64 t, %1; cvt.u32.u64 %0, t; }"
        : "=r"(a) : "l"(p));
    return a;
}

// ---------------- CSR build --------------------------------------------------
__global__ void k_zero_deg() {
    int i = blockIdx.x * blockDim.x + threadIdx.x;
    if (i < NN) g_deg[i] = 0;
}
__global__ void k_count(const int* __restrict__ dst) {
    int e = blockIdx.x * blockDim.x + threadIdx.x;
    if (e < NE) atomicAdd(&g_deg[dst[e]], 1);
}
__global__ void k_scan_block() {
    __shared__ int s[256];
    int t = threadIdx.x;
    int i = blockIdx.x * 256 + t;
    int v = (i < NN) ? g_deg[i] : 0;
    s[t] = v; __syncthreads();
#pragma unroll
    for (int off = 1; off < 256; off <<= 1) {
        int tv = (t >= off) ? s[t - off] : 0;
        __syncthreads();
        s[t] += tv;
        __syncthreads();
    }
    if (i < NN) g_rowoff[i] = s[t] - v;
    if (t == 255) g_blocksum[blockIdx.x] = s[255];
}
__global__ void k_scan_top(int nblocks) {
    __shared__ int s[512];
    int t = threadIdx.x;
    int v = (t < nblocks) ? g_blocksum[t] : 0;
    s[t] = v; __syncthreads();
    for (int off = 1; off < 512; off <<= 1) {
        int tv = (t >= off) ? s[t - off] : 0;
        __syncthreads();
        s[t] += tv;
        __syncthreads();
    }
    if (t < nblocks) g_blockoff[t] = s[t] - v;
}
__global__ void k_scan_add() {
    int i = blockIdx.x * 256 + threadIdx.x;
    if (i < NN) {
        int r = g_rowoff[i] + g_blockoff[blockIdx.x];
        g_rowoff[i] = r;
        g_cursor[i] = r;
    }
    if (i == 0) g_rowoff[NN] = NE;
}
__global__ void k_scatter(const int* __restrict__ src, const int* __restrict__ dst) {
    int e = blockIdx.x * blockDim.x + threadIdx.x;
    if (e < NE) {
        int p = atomicAdd(&g_cursor[dst[e]], 1);
        g_csr_src[p] = src[e];
    }
}

// ---------------- x -> fp16 copy ---------------------------------------------
__global__ void k_prep_x(const float* __restrict__ x, __half* __restrict__ xh) {
    int i = blockIdx.x * blockDim.x + threadIdx.x;      // float4 groups
    if (i < NN * DH / 4) {
        float4 v = *(const float4*)(x + (size_t)i * 4);
        __half2 h0 = __floats2half2_rn(v.x, v.y);
        __half2 h1 = __floats2half2_rn(v.z, v.w);
        uint2 p;
        p.x = *(u32*)&h0; p.y = *(u32*)&h1;
        *(uint2*)(xh + (size_t)i * 4) = p;
    }
}

// ---------------- mean aggregation: fp16 gather, one warp per node ----------
__global__ void k_agg(const __half* __restrict__ feat, float* __restrict__ out) {
    int w    = (blockIdx.x * blockDim.x + threadIdx.x) >> 5;
    int lane = threadIdx.x & 31;
    if (w >= NN) return;
    int beg = g_rowoff[w], end = g_rowoff[w + 1];
    float ax = 0.f, ay = 0.f, az = 0.f, aw = 0.f;
    int e = beg;
    for (; e + 4 <= end; e += 4) {                 // MLP = 4 on the gather
        int s0 = g_csr_src[e],     s1 = g_csr_src[e + 1];
        int s2 = g_csr_src[e + 2], s3 = g_csr_src[e + 3];
        uint2 r0 = *(const uint2*)(feat + (size_t)s0 * DH + lane * 4);
        uint2 r1 = *(const uint2*)(feat + (size_t)s1 * DH + lane * 4);
        uint2 r2 = *(const uint2*)(feat + (size_t)s2 * DH + lane * 4);
        uint2 r3 = *(const uint2*)(feat + (size_t)s3 * DH + lane * 4);
#pragma unroll
        for (int q = 0; q < 4; q++) {
            uint2 r = (q == 0) ? r0 : (q == 1) ? r1 : (q == 2) ? r2 : r3;
            float2 f0 = __half22float2(*(__half2*)&r.x);
            float2 f1 = __half22float2(*(__half2*)&r.y);
            ax += f0.x; ay += f0.y; az += f1.x; aw += f1.y;
        }
    }
    for (; e < end; e++) {
        int s0 = g_csr_src[e];
        uint2 r = *(const uint2*)(feat + (size_t)s0 * DH + lane * 4);
        float2 f0 = __half22float2(*(__half2*)&r.x);
        float2 f1 = __half22float2(*(__half2*)&r.y);
        ax += f0.x; ay += f0.y; az += f1.x; aw += f1.y;
    }
    int deg = end - beg;
    float inv = 1.0f / (float)(deg > 1 ? deg : 1);
    float4 r = make_float4(ax * inv, ay * inv, az * inv, aw * inv);
    *(float4*)(out + (size_t)w * DH + lane * 4) = r;
}

// ---------------- weight prep: transpose + bf16 hi/lo split -----------------
__global__ void k_prep_w(const float* __restrict__ Wn0, const float* __restrict__ Wr0,
                         const float* __restrict__ Wn1, const float* __restrict__ Wr1) {
    int idx = blockIdx.x * blockDim.x + threadIdx.x;   // 0..65535
    int mat = idx >> 14;
    int e   = idx & 16383;
    int n = e >> 7, k = e & 127;
    const float* W = (mat == 0) ? Wn0 : (mat == 1) ? Wr0 : (mat == 2) ? Wn1 : Wr1;
    float v = W[k * 128 + n];                          // B[n][k] = W[k][n]
    __nv_bfloat16 hi = __float2bfloat16(v);
    float lof = v - __bfloat162float(hi);
    __nv_bfloat16 lo = __float2bfloat16(lof);
    g_wimg[2 * mat][n * 128 + k]     = __bfloat16_as_ushort(hi);
    g_wimg[2 * mat + 1][n * 128 + k] = __bfloat16_as_ushort(lo);
}

// ---------------- tensor-core fused dual GEMM (mma.sync, 3xBF16) ------------
// Hout = relu( Aagg @ Wn + Hin @ Wr + bias )
// If Wh != nullptr: fused head, writes out[row] = relu_row . Wh + bh (no Hout).
// Else: writes Hout (fp32) and HoutH (fp16 copy for next gather).
__device__ __forceinline__ void ldm_x4(u32& r0, u32& r1, u32& r2, u32& r3, u32 addr) {
    asm volatile("ldmatrix.sync.aligned.m8n8.x4.shared.b16 {%0,%1,%2,%3}, [%4];"
                 : "=r"(r0), "=r"(r1), "=r"(r2), "=r"(r3) : "r"(addr));
}
__device__ __forceinline__ void mma16816(float* c, const u32* a, u32 b0, u32 b1) {
    asm volatile(
        "mma.sync.aligned.m16n8k16.row.col.f32.bf16.bf16.f32 "
        "{%0,%1,%2,%3},{%4,%5,%6,%7},{%8,%9},{%0,%1,%2,%3};"
        : "+f"(c[0]), "+f"(c[1]), "+f"(c[2]), "+f"(c[3])
        : "r"(a[0]), "r"(a[1]), "r"(a[2]), "r"(a[3]), "r"(b0), "r"(b1));
}

__global__ __launch_bounds__(256, 2)
void k_gemm_mma(const float* __restrict__ Aagg, const float* __restrict__ Hin,
                const u16* __restrict__ BnH, const u16* __restrict__ BnL,
                const u16* __restrict__ BrH, const u16* __restrict__ BrL,
                const float* __restrict__ bias,
                float* __restrict__ Hout, __half* __restrict__ HoutH,
                const float* __restrict__ Wh, const float* __restrict__ bh,
                float* __restrict__ out)
{
    __shared__ u16 AsH[128 * SB], AsL[128 * SB], BsH[128 * SB], BsL[128 * SB];
    __shared__ float HeadPart[2][128];
    const int tid = threadIdx.x, wid = tid >> 5, lane = tid & 31;
    const int blockRow = blockIdx.x * 128;
    const int warpR = (wid & 3) * 32;     // 4 M-warps
    const int warpC = (wid >> 2) * 64;    // 2 N-warps

    const u32 ah_b = smem_u32(AsH), al_b = smem_u32(AsL);
    const u32 bh_b = smem_u32(BsH), bl_b = smem_u32(BsL);

    float acc[2][8][4];
#pragma unroll
    for (int i = 0; i < 2; i++)
#pragma unroll
        for (int j = 0; j < 8; j++)
#pragma unroll
            for (int q = 0; q < 4; q++) acc[i][j][q] = 0.f;

    const int arow = tid >> 1, acol = (tid & 1) * 16;
    const int agrow = blockRow + arow;

#pragma unroll
    for (int half = 0; half < 2; half++) {
        const float* src = half ? Hin : Aagg;
        const u16* WH = half ? BrH : BnH;
        const u16* WL = half ? BrL : BnL;

        for (int kc = 0; kc < 4; kc++) {
            __syncthreads();   // previous chunk fully consumed
            // ---- A: fp32 -> bf16 hi/lo into padded smem tiles ----
            {
                const float* rp = src + (size_t)agrow * DH + kc * 32 + acol;
#pragma unroll
                for (int c = 0; c < 4; c++) {
                    float4 v = (agrow < NN) ? *(const float4*)(rp + c * 4)
                                            : make_float4(0.f, 0.f, 0.f, 0.f);
                    __nv_bfloat16 h0 = __float2bfloat16(v.x);
                    __nv_bfloat16 h1 = __float2bfloat16(v.y);
                    __nv_bfloat16 h2 = __float2bfloat16(v.z);
                    __nv_bfloat16 h3 = __float2bfloat16(v.w);
                    __nv_bfloat16 l0 = __float2bfloat16(v.x - __bfloat162float(h0));
                    __nv_bfloat16 l1 = __float2bfloat16(v.y - __bfloat162float(h1));
                    __nv_bfloat16 l2 = __float2bfloat16(v.z - __bfloat162float(h2));
                    __nv_bfloat16 l3 = __float2bfloat16(v.w - __bfloat162float(h3));
                    uint2 ph, pl;
                    ph.x = (u32)__bfloat16_as_ushort(h0) | ((u32)__bfloat16_as_ushort(h1) << 16);
                    ph.y = (u32)__bfloat16_as_ushort(h2) | ((u32)__bfloat16_as_ushort(h3) << 16);
                    pl.x = (u32)__bfloat16_as_ushort(l0) | ((u32)__bfloat16_as_ushort(l1) << 16);
                    pl.y = (u32)__bfloat16_as_ushort(l2) | ((u32)__bfloat16_as_ushort(l3) << 16);
                    int off = arow * SB + acol + c * 4;
                    *(uint2*)&AsH[off] = ph;
                    *(uint2*)&AsL[off] = pl;
                }
            }
            // ---- B: copy k-chunk of the hi/lo weight images ----
            {
#pragma unroll
                for (int i = 0; i < 4; i++) {
                    int p = tid + i * 256;          // 0..1023
                    int img = p >> 9;               // 0 = hi, 1 = lo
                    int idx = p & 511;
                    int n = idx >> 2, part = idx & 3;
                    const u16* s = (img ? WL : WH) + n * 128 + kc * 32 + part * 8;
                    u16* d = (img ? BsL : BsH) + n * SB + part * 8;
                    *(uint4*)d = *(const uint4*)s;
                }
            }
            __syncthreads();

            // ---- compute: 3 passes x 2 k-steps x 16 mma ----
#pragma unroll
            for (int p = 0; p < 3; p++) {
                u32 a_base = (p == 2) ? al_b : ah_b;
                u32 b_base = (p == 1) ? bl_b : bh_b;
#pragma unroll
                for (int ks = 0; ks < 2; ks++) {
                    int k0 = ks * 16;
                    u32 afrag[2][4];
#pragma unroll
                    for (int mi = 0; mi < 2; mi++) {
                        int rowA = warpR + mi * 16 + (lane & 15);
                        int colA = k0 + ((lane >> 4) << 3);
                        ldm_x4(afrag[mi][0], afrag[mi][1], afrag[mi][2], afrag[mi][3],
                               a_base + (u32)(rowA * SB + colA) * 2);
                    }
                    u32 bfrag[4][4];
#pragma unroll
                    for (int pj = 0; pj < 4; pj++) {
                        int nB = warpC + pj * 16 + ((lane >> 4) << 3) + (lane & 7);
                        int kB = k0 + (lane & 8);
                        ldm_x4(bfrag[pj][0], bfrag[pj][1], bfrag[pj][2], bfrag[pj][3],
                               b_base + (u32)(nB * SB + kB) * 2);
                    }
#pragma unroll
                    for (int mi = 0; mi < 2; mi++)
#pragma unroll
                        for (int nj = 0; nj < 8; nj++) {
                            const u32* bp = bfrag[nj >> 1];
                            u32 b0 = (nj & 1) ? bp[2] : bp[0];
                            u32 b1 = (nj & 1) ? bp[3] : bp[1];
                            mma16816(acc[mi][nj], afrag[mi], b0, b1);
                        }
                }
            }
        }
    }

    // ---- epilogue ----
    const int g = lane >> 2, tg = lane & 3;
    if (Wh == nullptr) {
        // bias + relu + store fp32 and fp16 copies
#pragma unroll
        for (int mi = 0; mi < 2; mi++) {
            int row0 = blockRow + warpR + mi * 16 + g;
            int row1 = row0 + 8;
#pragma unroll
            for (int nj = 0; nj < 8; nj++) {
                int col = warpC + nj * 8 + tg * 2;
                float b0v = bias[col], b1v = bias[col + 1];
                if (row0 < NN) {
                    float2 o;
                    o.x = fmaxf(acc[mi][nj][0] + b0v, 0.f);
                    o.y = fmaxf(acc[mi][nj][1] + b1v, 0.f);
                    *(float2*)(Hout + (size_t)row0 * DH + col) = o;
                    *(__half2*)(HoutH + (size_t)row0 * DH + col) = __floats2half2_rn(o.x, o.y);
                }
                if (row1 < NN) {
                    float2 o;
                    o.x = fmaxf(acc[mi][nj][2] + b0v, 0.f);
                    o.y = fmaxf(acc[mi][nj][3] + b1v, 0.f);
                    *(float2*)(Hout + (size_t)row1 * DH + col) = o;
                    *(__half2*)(HoutH + (size_t)row1 * DH + col) = __floats2half2_rn(o.x, o.y);
                }
            }
        }
    } else {
        // fused head: out[row] = relu(row) . Wh + bh  (deterministic smem combine)
        float p0[2] = {0.f, 0.f}, p1[2] = {0.f, 0.f};   // [mi] for row-lo / row-hi
#pragma unroll
        for (int mi = 0; mi < 2; mi++) {
#pragma unroll
            for (int nj = 0; nj < 8; nj++) {
                int col = warpC + nj * 8 + tg * 2;
                float b0v = bias[col], b1v = bias[col + 1];
                float w0 = Wh[col], w1 = Wh[col + 1];
                p0[mi] += fmaxf(acc[mi][nj][0] + b0v, 0.f) * w0
                        + fmaxf(acc[mi][nj][1] + b1v, 0.f) * w1;
                p1[mi] += fmaxf(acc[mi][nj][2] + b0v, 0.f) * w0
                        + fmaxf(acc[mi][nj][3] + b1v, 0.f) * w1;
            }
        }
#pragma unroll
        for (int off = 1; off <= 2; off <<= 1) {
#pragma unroll
            for (int mi = 0; mi < 2; mi++) {
                p0[mi] += __shfl_xor_sync(0xFFFFFFFFu, p0[mi], off);
                p1[mi] += __shfl_xor_sync(0xFFFFFFFFu, p1[mi], off);
            }
        }
        if (tg == 0) {
#pragma unroll
            for (int mi = 0; mi < 2; mi++) {
                HeadPart[wid >> 2][warpR + mi * 16 + g]     = p0[mi];
                HeadPart[wid >> 2][warpR + mi * 16 + g + 8] = p1[mi];
            }
        }
        __syncthreads();
        if (tid < 128) {
            int r = blockRow + tid;
            if (r < NN) out[r] = HeadPart[0][tid] + HeadPart[1][tid] + bh[0];
        }
    }
}

// ---------------- launch -----------------------------------------------------
extern "C" void kernel_launch(void* const* d_in, const int* in_sizes, int n_in,
                              void* d_out, int out_size) {
    const float* x   = (const float*)d_in[0];
    const int*   ei  = (const int*)  d_in[1];
    const int*   src = ei;
    const int*   dst = ei + NE;
    const float* Wn0 = (const float*)d_in[2];
    const float* Wr0 = (const float*)d_in[3];
    const float* b0  = (const float*)d_in[4];
    const float* Wn1 = (const float*)d_in[5];
    const float* Wr1 = (const float*)d_in[6];
    const float* b1  = (const float*)d_in[7];
    const float* Wh  = (const float*)d_in[8];
    const float* bh  = (const float*)d_in[9];
    float* out = (float*)d_out;

    float *agg, *h1;
    __half *xh, *h1h;
    u16* wimg;
    cudaGetSymbolAddress((void**)&agg,  g_agg);
    cudaGetSymbolAddress((void**)&h1,   g_h1);
    cudaGetSymbolAddress((void**)&xh,   g_xh);
    cudaGetSymbolAddress((void**)&h1h,  g_h1h);
    cudaGetSymbolAddress((void**)&wimg, g_wimg);

    const int NB_N = (NN + 255) / 256;
    const int NB_E = (NE + 255) / 256;
    const int NB_W = (NN * 32 + 255) / 256;
    const int NB_X = (NN * DH / 4 + 255) / 256;

    // CSR build
    k_zero_deg  <<<NB_N, 256>>>();
    k_count     <<<NB_E, 256>>>(dst);
    k_scan_block<<<NB_N, 256>>>();
    k_scan_top  <<<1,   512>>>(NB_N);
    k_scan_add  <<<NB_N, 256>>>();
    k_scatter   <<<NB_E, 256>>>(src, dst);

    // preps
    k_prep_w<<<256, 256>>>(Wn0, Wr0, Wn1, Wr1);
    k_prep_x<<<NB_X, 256>>>(x, xh);

    // layer 0
    k_agg     <<<NB_W, 256>>>(xh, agg);
    k_gemm_mma<<<NTILES, 256>>>(agg, x,
        wimg + 0 * 16384, wimg + 1 * 16384, wimg + 2 * 16384, wimg + 3 * 16384,
        b0, h1, h1h, nullptr, nullptr, nullptr);
    // layer 1 + fused head
    k_agg     <<<NB_W, 256>>>(h1h, agg);
    k_gemm_mma<<<NTILES, 256>>>(agg, h1,
        wimg + 4 * 16384, wimg + 5 * 16384, wimg + 6 * 16384, wimg + 7 * 16384,
        b1, nullptr, nullptr, Wh, bh, out);
}

// round 6
// speedup vs baseline: 2.1177x; 1.3267x over previous
#include <cuda_runtime.h>
#include <cuda_fp16.h>
#include <cstdint>

#define NN 100000
#define NE 1600000
#define DH 128
#define NTILES ((NN + 127) / 128)
#define SB 40   // padded smem row stride (fp16 elems): 80B -> conflict-free ldmatrix

typedef unsigned int u32;
typedef unsigned short u16;

// ---------------- scratch (device globals: no allocation allowed) -----------
__device__ int    g_deg[NN];
__device__ int    g_rowoff[NN + 1];
__device__ int    g_cursor[NN];
__device__ int    g_blocksum[512];
__device__ int    g_blockoff[512];
__device__ int    g_csr_src[NE];
__device__ float  g_agg[(size_t)NN * DH];
__device__ __half g_xh [(size_t)NN * DH];   // fp16 copy of x   (gather + root L0)
__device__ __half g_h1h[(size_t)NN * DH];   // fp16 h1          (gather + root L1)
// 4 fp16 weight images, [n][k] row-major 128x128: Wn0, Wr0, Wn1, Wr1 (transposed)
__device__ u16 g_wimg[4][16384];

__device__ __forceinline__ u32 smem_u32(const void* p) {
    u32 a;
    asm("{ .reg .u64 t; cvta.to.shared.u64 t, %1; cvt.u32.u64 %0, t; }"
        : "=r"(a) : "l"(p));
    return a;
}

// ---------------- CSR build --------------------------------------------------
__global__ void k_zero_deg() {
    int i = blockIdx.x * blockDim.x + threadIdx.x;
    if (i < NN) g_deg[i] = 0;
}
__global__ void k_count(const int* __restrict__ dst) {
    int e = blockIdx.x * blockDim.x + threadIdx.x;
    if (e < NE) atomicAdd(&g_deg[dst[e]], 1);
}
__global__ void k_scan_block() {
    __shared__ int s[256];
    int t = threadIdx.x;
    int i = blockIdx.x * 256 + t;
    int v = (i < NN) ? g_deg[i] : 0;
    s[t] = v; __syncthreads();
#pragma unroll
    for (int off = 1; off < 256; off <<= 1) {
        int tv = (t >= off) ? s[t - off] : 0;
        __syncthreads();
        s[t] += tv;
        __syncthreads();
    }
    if (i < NN) g_rowoff[i] = s[t] - v;
    if (t == 255) g_blocksum[blockIdx.x] = s[255];
}
__global__ void k_scan_top(int nblocks) {
    __shared__ int s[512];
    int t = threadIdx.x;
    int v = (t < nblocks) ? g_blocksum[t] : 0;
    s[t] = v; __syncthreads();
    for (int off = 1; off < 512; off <<= 1) {
        int tv = (t >= off) ? s[t - off] : 0;
        __syncthreads();
        s[t] += tv;
        __syncthreads();
    }
    if (t < nblocks) g_blockoff[t] = s[t] - v;
}
__global__ void k_scan_add() {
    int i = blockIdx.x * 256 + threadIdx.x;
    if (i < NN) {
        int r = g_rowoff[i] + g_blockoff[blockIdx.x];
        g_rowoff[i] = r;
        g_cursor[i] = r;
    }
    if (i == 0) g_rowoff[NN] = NE;
}
__global__ void k_scatter(const int* __restrict__ src, const int* __restrict__ dst) {
    int e = blockIdx.x * blockDim.x + threadIdx.x;
    if (e < NE) {
        int p = atomicAdd(&g_cursor[dst[e]], 1);
        g_csr_src[p] = src[e];
    }
}

// ---------------- x -> fp16 copy ---------------------------------------------
__global__ void k_prep_x(const float* __restrict__ x, __half* __restrict__ xh) {
    int i = blockIdx.x * blockDim.x + threadIdx.x;      // float4 groups
    if (i < NN * DH / 4) {
        float4 v = *(const float4*)(x + (size_t)i * 4);
        __half2 h0 = __floats2half2_rn(v.x, v.y);
        __half2 h1 = __floats2half2_rn(v.z, v.w);
        uint2 p;
        p.x = *(u32*)&h0; p.y = *(u32*)&h1;
        *(uint2*)(xh + (size_t)i * 4) = p;
    }
}

// ---------------- mean aggregation: fp16 gather, one warp per node ----------
__global__ void k_agg(const __half* __restrict__ feat, float* __restrict__ out) {
    int w    = (blockIdx.x * blockDim.x + threadIdx.x) >> 5;
    int lane = threadIdx.x & 31;
    if (w >= NN) return;
    int beg = g_rowoff[w], end = g_rowoff[w + 1];
    float ax = 0.f, ay = 0.f, az = 0.f, aw = 0.f;
    int e = beg;
    for (; e + 4 <= end; e += 4) {                 // MLP = 4 on the gather
        int s0 = g_csr_src[e],     s1 = g_csr_src[e + 1];
        int s2 = g_csr_src[e + 2], s3 = g_csr_src[e + 3];
        uint2 r0 = *(const uint2*)(feat + (size_t)s0 * DH + lane * 4);
        uint2 r1 = *(const uint2*)(feat + (size_t)s1 * DH + lane * 4);
        uint2 r2 = *(const uint2*)(feat + (size_t)s2 * DH + lane * 4);
        uint2 r3 = *(const uint2*)(feat + (size_t)s3 * DH + lane * 4);
#pragma unroll
        for (int q = 0; q < 4; q++) {
            uint2 r = (q == 0) ? r0 : (q == 1) ? r1 : (q == 2) ? r2 : r3;
            float2 f0 = __half22float2(*(__half2*)&r.x);
            float2 f1 = __half22float2(*(__half2*)&r.y);
            ax += f0.x; ay += f0.y; az += f1.x; aw += f1.y;
        }
    }
    for (; e < end; e++) {
        int s0 = g_csr_src[e];
        uint2 r = *(const uint2*)(feat + (size_t)s0 * DH + lane * 4);
        float2 f0 = __half22float2(*(__half2*)&r.x);
        float2 f1 = __half22float2(*(__half2*)&r.y);
        ax += f0.x; ay += f0.y; az += f1.x; aw += f1.y;
    }
    int deg = end - beg;
    float inv = 1.0f / (float)(deg > 1 ? deg : 1);
    float4 r = make_float4(ax * inv, ay * inv, az * inv, aw * inv);
    *(float4*)(out + (size_t)w * DH + lane * 4) = r;
}

// ---------------- weight prep: transpose + fp16 ------------------------------
__global__ void k_prep_w(const float* __restrict__ Wn0, const float* __restrict__ Wr0,
                         const float* __restrict__ Wn1, const float* __restrict__ Wr1) {
    int idx = blockIdx.x * blockDim.x + threadIdx.x;   // 0..65535
    int mat = idx >> 14;
    int e   = idx & 16383;
    int n = e >> 7, k = e & 127;
    const float* W = (mat == 0) ? Wn0 : (mat == 1) ? Wr0 : (mat == 2) ? Wn1 : Wr1;
    float v = W[k * 128 + n];                          // B[n][k] = W[k][n]
    __half h = __float2half_rn(v);
    g_wimg[mat][n * 128 + k] = __half_as_ushort(h);
}

// ---------------- MMA primitives ---------------------------------------------
__device__ __forceinline__ void ldm_x4(u32& r0, u32& r1, u32& r2, u32& r3, u32 addr) {
    asm volatile("ldmatrix.sync.aligned.m8n8.x4.shared.b16 {%0,%1,%2,%3}, [%4];"
                 : "=r"(r0), "=r"(r1), "=r"(r2), "=r"(r3) : "r"(addr));
}
__device__ __forceinline__ void mma16816(float* c, const u32* a, u32 b0, u32 b1) {
    asm volatile(
        "mma.sync.aligned.m16n8k16.row.col.f32.f16.f16.f32 "
        "{%0,%1,%2,%3},{%4,%5,%6,%7},{%8,%9},{%0,%1,%2,%3};"
        : "+f"(c[0]), "+f"(c[1]), "+f"(c[2]), "+f"(c[3])
        : "r"(a[0]), "r"(a[1]), "r"(a[2]), "r"(a[3]), "r"(b0), "r"(b1));
}

// ---------------- GEMM core (shared by mid/head kernels) ---------------------
// acc += Aagg(fp32, hi/lo fp16 split, 2 passes) @ Wn  +  RootH(fp16, 1 pass) @ Wr
struct GemmSmem {
    u16 AsH[128 * SB];
    u16 AsL[128 * SB];
    u16 Bs [128 * SB];
};

__device__ __forceinline__ void gemm_core(
    GemmSmem& sm, const float* __restrict__ Aagg, const __half* __restrict__ RootH,
    const u16* __restrict__ Bn, const u16* __restrict__ Br,
    int blockRow, int tid, int wid, int lane, int warpR, int warpC,
    float acc[2][8][4])
{
    const u32 ah_b = smem_u32(sm.AsH), al_b = smem_u32(sm.AsL), b_b = smem_u32(sm.Bs);
    const int arow = tid >> 1, acol = (tid & 1) * 16;
    const int agrow = blockRow + arow;

#pragma unroll
    for (int half = 0; half < 2; half++) {
        const u16* Bimg = half ? Br : Bn;
        const int passes = half ? 1 : 2;

        for (int kc = 0; kc < 4; kc++) {
            __syncthreads();   // previous chunk fully consumed
            // ---- A fill ----
            if (half == 0) {
                // fp32 agg -> fp16 hi/lo (16 elems per thread)
                const float* rp = Aagg + (size_t)agrow * DH + kc * 32 + acol;
#pragma unroll
                for (int c = 0; c < 4; c++) {
                    float4 v = (agrow < NN) ? *(const float4*)(rp + c * 4)
                                            : make_float4(0.f, 0.f, 0.f, 0.f);
                    __half h0 = __float2half_rn(v.x);
                    __half h1 = __float2half_rn(v.y);
                    __half h2 = __float2half_rn(v.z);
                    __half h3 = __float2half_rn(v.w);
                    __half l0 = __float2half_rn(v.x - __half2float(h0));
                    __half l1 = __float2half_rn(v.y - __half2float(h1));
                    __half l2 = __float2half_rn(v.z - __half2float(h2));
                    __half l3 = __float2half_rn(v.w - __half2float(h3));
                    uint2 ph, pl;
                    ph.x = (u32)__half_as_ushort(h0) | ((u32)__half_as_ushort(h1) << 16);
                    ph.y = (u32)__half_as_ushort(h2) | ((u32)__half_as_ushort(h3) << 16);
                    pl.x = (u32)__half_as_ushort(l0) | ((u32)__half_as_ushort(l1) << 16);
                    pl.y = (u32)__half_as_ushort(l2) | ((u32)__half_as_ushort(l3) << 16);
                    int off = arow * SB + acol + c * 4;
                    *(uint2*)&sm.AsH[off] = ph;
                    *(uint2*)&sm.AsL[off] = pl;
                }
            } else {
                // fp16 root: straight copy of ALL 16 elems (2 x uint4 = 16 halves).
                // (R5 bug: single uint4 copied only 8, leaving 8 stale -> rel_err 0.5)
                const __half* rp = RootH + (size_t)agrow * DH + kc * 32 + acol;
                uint4 v0 = make_uint4(0, 0, 0, 0), v1 = make_uint4(0, 0, 0, 0);
                if (agrow < NN) {
                    v0 = *(const uint4*)(rp);
                    v1 = *(const uint4*)(rp + 8);
                }
                *(uint4*)&sm.AsH[arow * SB + acol]     = v0;
                *(uint4*)&sm.AsH[arow * SB + acol + 8] = v1;
            }
            // ---- B fill: 8KB chunk of weight image ----
#pragma unroll
            for (int i = 0; i < 2; i++) {
                int p = tid + i * 256;          // 0..511
                int n = p >> 2, part = p & 3;
                *(uint4*)&sm.Bs[n * SB + part * 8] =
                    *(const uint4*)(Bimg + n * 128 + kc * 32 + part * 8);
            }
            __syncthreads();

            // ---- compute ----
            for (int p = 0; p < passes; p++) {
                u32 a_base = p ? al_b : ah_b;
#pragma unroll
                for (int ks = 0; ks < 2; ks++) {
                    int k0 = ks * 16;
                    u32 afrag[2][4];
#pragma unroll
                    for (int mi = 0; mi < 2; mi++) {
                        int rowA = warpR + mi * 16 + (lane & 15);
                        int colA = k0 + ((lane >> 4) << 3);
                        ldm_x4(afrag[mi][0], afrag[mi][1], afrag[mi][2], afrag[mi][3],
                               a_base + (u32)(rowA * SB + colA) * 2);
                    }
                    u32 bfrag[4][4];
#pragma unroll
                    for (int pj = 0; pj < 4; pj++) {
                        int nB = warpC + pj * 16 + ((lane >> 4) << 3) + (lane & 7);
                        int kB = k0 + (lane & 8);
                        ldm_x4(bfrag[pj][0], bfrag[pj][1], bfrag[pj][2], bfrag[pj][3],
                               b_b + (u32)(nB * SB + kB) * 2);
                    }
#pragma unroll
                    for (int mi = 0; mi < 2; mi++)
#pragma unroll
                        for (int nj = 0; nj < 8; nj++) {
                            const u32* bp = bfrag[nj >> 1];
                            u32 b0 = (nj & 1) ? bp[2] : bp[0];
                            u32 b1 = (nj & 1) ? bp[3] : bp[1];
                            mma16816(acc[mi][nj], afrag[mi], b0, b1);
                        }
                }
            }
        }
    }
}

// ---------------- GEMM kernel: mid layer (fp16 hidden out) -------------------
__global__ __launch_bounds__(256, 2)
void k_gemm_mid(const float* __restrict__ Aagg, const __half* __restrict__ RootH,
                const u16* __restrict__ Bn, const u16* __restrict__ Br,
                const float* __restrict__ bias, __half* __restrict__ HoutH)
{
    __shared__ GemmSmem sm;
    const int tid = threadIdx.x, wid = tid >> 5, lane = tid & 31;
    const int blockRow = blockIdx.x * 128;
    const int warpR = (wid & 3) * 32, warpC = (wid >> 2) * 64;

    float acc[2][8][4];
#pragma unroll
    for (int i = 0; i < 2; i++)
#pragma unroll
        for (int j = 0; j < 8; j++)
#pragma unroll
            for (int q = 0; q < 4; q++) acc[i][j][q] = 0.f;

    gemm_core(sm, Aagg, RootH, Bn, Br, blockRow, tid, wid, lane, warpR, warpC, acc);

    const int g = lane >> 2, tg = lane & 3;
#pragma unroll
    for (int mi = 0; mi < 2; mi++) {
        int row0 = blockRow + warpR + mi * 16 + g;
        int row1 = row0 + 8;
#pragma unroll
        for (int nj = 0; nj < 8; nj++) {
            int col = warpC + nj * 8 + tg * 2;
            float b0v = bias[col], b1v = bias[col + 1];
            if (row0 < NN)
                *(__half2*)(HoutH + (size_t)row0 * DH + col) =
                    __floats2half2_rn(fmaxf(acc[mi][nj][0] + b0v, 0.f),
                                      fmaxf(acc[mi][nj][1] + b1v, 0.f));
            if (row1 < NN)
                *(__half2*)(HoutH + (size_t)row1 * DH + col) =
                    __floats2half2_rn(fmaxf(acc[mi][nj][2] + b0v, 0.f),
                                      fmaxf(acc[mi][nj][3] + b1v, 0.f));
        }
    }
}

// ---------------- GEMM kernel: last layer + fused head -----------------------
__global__ __launch_bounds__(256, 2)
void k_gemm_head(const float* __restrict__ Aagg, const __half* __restrict__ RootH,
                 const u16* __restrict__ Bn, const u16* __restrict__ Br,
                 const float* __restrict__ bias,
                 const float* __restrict__ Wh, const float* __restrict__ bh,
                 float* __restrict__ out)
{
    __shared__ GemmSmem sm;
    __shared__ float HeadPart[2][128];
    const int tid = threadIdx.x, wid = tid >> 5, lane = tid & 31;
    const int blockRow = blockIdx.x * 128;
    const int warpR = (wid & 3) * 32, warpC = (wid >> 2) * 64;

    float acc[2][8][4];
#pragma unroll
    for (int i = 0; i < 2; i++)
#pragma unroll
        for (int j = 0; j < 8; j++)
#pragma unroll
            for (int q = 0; q < 4; q++) acc[i][j][q] = 0.f;

    gemm_core(sm, Aagg, RootH, Bn, Br, blockRow, tid, wid, lane, warpR, warpC, acc);

    const int g = lane >> 2, tg = lane & 3;
    float p0[2] = {0.f, 0.f}, p1[2] = {0.f, 0.f};
#pragma unroll
    for (int mi = 0; mi < 2; mi++) {
#pragma unroll
        for (int nj = 0; nj < 8; nj++) {
            int col = warpC + nj * 8 + tg * 2;
            float b0v = bias[col], b1v = bias[col + 1];
            float w0 = Wh[col], w1 = Wh[col + 1];
            p0[mi] += fmaxf(acc[mi][nj][0] + b0v, 0.f) * w0
                    + fmaxf(acc[mi][nj][1] + b1v, 0.f) * w1;
            p1[mi] += fmaxf(acc[mi][nj][2] + b0v, 0.f) * w0
                    + fmaxf(acc[mi][nj][3] + b1v, 0.f) * w1;
        }
    }
#pragma unroll
    for (int off = 1; off <= 2; off <<= 1) {
#pragma unroll
        for (int mi = 0; mi < 2; mi++) {
            p0[mi] += __shfl_xor_sync(0xFFFFFFFFu, p0[mi], off);
            p1[mi] += __shfl_xor_sync(0xFFFFFFFFu, p1[mi], off);
        }
    }
    if (tg == 0) {
#pragma unroll
        for (int mi = 0; mi < 2; mi++) {
            HeadPart[wid >> 2][warpR + mi * 16 + g]     = p0[mi];
            HeadPart[wid >> 2][warpR + mi * 16 + g + 8] = p1[mi];
        }
    }
    __syncthreads();
    if (tid < 128) {
        int r = blockRow + tid;
        if (r < NN) out[r] = HeadPart[0][tid] + HeadPart[1][tid] + bh[0];
    }
}

// ---------------- launch -----------------------------------------------------
extern "C" void kernel_launch(void* const* d_in, const int* in_sizes, int n_in,
                              void* d_out, int out_size) {
    const float* x   = (const float*)d_in[0];
    const int*   ei  = (const int*)  d_in[1];
    const int*   src = ei;
    const int*   dst = ei + NE;
    const float* Wn0 = (const float*)d_in[2];
    const float* Wr0 = (const float*)d_in[3];
    const float* b0  = (const float*)d_in[4];
    const float* Wn1 = (const float*)d_in[5];
    const float* Wr1 = (const float*)d_in[6];
    const float* b1  = (const float*)d_in[7];
    const float* Wh  = (const float*)d_in[8];
    const float* bh  = (const float*)d_in[9];
    float* out = (float*)d_out;

    float *agg;
    __half *xh, *h1h;
    u16* wimg;
    cudaGetSymbolAddress((void**)&agg,  g_agg);
    cudaGetSymbolAddress((void**)&xh,   g_xh);
    cudaGetSymbolAddress((void**)&h1h,  g_h1h);
    cudaGetSymbolAddress((void**)&wimg, g_wimg);

    const int NB_N = (NN + 255) / 256;
    const int NB_E = (NE + 255) / 256;
    const int NB_W = (NN * 32 + 255) / 256;
    const int NB_X = (NN * DH / 4 + 255) / 256;

    // CSR build
    k_zero_deg  <<<NB_N, 256>>>();
    k_count     <<<NB_E, 256>>>(dst);
    k_scan_block<<<NB_N, 256>>>();
    k_scan_top  <<<1,   512>>>(NB_N);
    k_scan_add  <<<NB_N, 256>>>();
    k_scatter   <<<NB_E, 256>>>(src, dst);

    // preps
    k_prep_w<<<256, 256>>>(Wn0, Wr0, Wn1, Wr1);
    k_prep_x<<<NB_X, 256>>>(x, xh);

    // layer 0
    k_agg     <<<NB_W, 256>>>(xh, agg);
    k_gemm_mid<<<NTILES, 256>>>(agg, xh,
        wimg + 0 * 16384, wimg + 1 * 16384, b0, h1h);
    // layer 1 + fused head
    k_agg      <<<NB_W, 256>>>(h1h, agg);
    k_gemm_head<<<NTILES, 256>>>(agg, h1h,
        wimg + 2 * 16384, wimg + 3 * 16384, b1, Wh, bh, out);
}

// round 7
// speedup vs baseline: 2.4185x; 1.1420x over previous
#include <cuda_runtime.h>
#include <cuda_fp16.h>
#include <cstdint>

#define NN 100000
#define NE 1600000
#define DH 128
#define NTILES ((NN + 127) / 128)
#define SB 72   // padded smem row stride (fp16): 144B -> conflict-free ldmatrix

typedef unsigned int u32;
typedef unsigned short u16;

// ---------------- scratch (device globals: no allocation allowed) -----------
__device__ int    g_deg[NN];
__device__ int    g_rowoff[NN + 1];
__device__ int    g_cursor[NN];
__device__ int    g_blocksum[512];
__device__ int    g_blockoff[512];
__device__ int    g_csr_src[NE];
__device__ __half g_aggh[(size_t)NN * DH];  // fp16 aggregation result
__device__ __half g_xh  [(size_t)NN * DH];  // fp16 copy of x   (gather + root L0)
__device__ __half g_h1h [(size_t)NN * DH];  // fp16 h1          (gather + root L1)
// 4 fp16 weight images, [n][k] row-major 128x128: Wn0, Wr0, Wn1, Wr1 (transposed)
__device__ u16 g_wimg[4][16384];

__device__ __forceinline__ u32 smem_u32(const void* p) {
    u32 a;
    asm("{ .reg .u64 t; cvta.to.shared.u64 t, %1; cvt.u32.u64 %0, t; }"
        : "=r"(a) : "l"(p));
    return a;
}

// ---------------- CSR build --------------------------------------------------
__global__ void k_count(const int* __restrict__ dst) {
    int e = blockIdx.x * blockDim.x + threadIdx.x;
    if (e < NE) atomicAdd(&g_deg[dst[e]], 1);
}
__global__ void k_scan_block() {
    __shared__ int s[256];
    int t = threadIdx.x;
    int i = blockIdx.x * 256 + t;
    int v = (i < NN) ? g_deg[i] : 0;
    s[t] = v; __syncthreads();
#pragma unroll
    for (int off = 1; off < 256; off <<= 1) {
        int tv = (t >= off) ? s[t - off] : 0;
        __syncthreads();
        s[t] += tv;
        __syncthreads();
    }
    if (i < NN) g_rowoff[i] = s[t] - v;
    if (t == 255) g_blocksum[blockIdx.x] = s[255];
}
__global__ void k_scan_top(int nblocks) {
    __shared__ int s[512];
    int t = threadIdx.x;
    int v = (t < nblocks) ? g_blocksum[t] : 0;
    s[t] = v; __syncthreads();
    for (int off = 1; off < 512; off <<= 1) {
        int tv = (t >= off) ? s[t - off] : 0;
        __syncthreads();
        s[t] += tv;
        __syncthreads();
    }
    if (t < nblocks) g_blockoff[t] = s[t] - v;
}
__global__ void k_scan_add() {
    int i = blockIdx.x * 256 + threadIdx.x;
    if (i < NN) {
        int r = g_rowoff[i] + g_blockoff[blockIdx.x];
        g_rowoff[i] = r;
        g_cursor[i] = r;
    }
    if (i == 0) g_rowoff[NN] = NE;
}
__global__ void k_scatter(const int* __restrict__ src, const int* __restrict__ dst) {
    int e = blockIdx.x * blockDim.x + threadIdx.x;
    if (e < NE) {
        int p = atomicAdd(&g_cursor[dst[e]], 1);
        g_csr_src[p] = src[e];
    }
}

// ---------------- fused prep: x->fp16, weights transpose+fp16, deg zero -----
__global__ void k_prep(const float* __restrict__ x,
                       const float* __restrict__ Wn0, const float* __restrict__ Wr0,
                       const float* __restrict__ Wn1, const float* __restrict__ Wr1) {
    int i = blockIdx.x * blockDim.x + threadIdx.x;
    if (i < NN * DH / 4) {                              // x -> fp16 (float4 groups)
        float4 v = *(const float4*)(x + (size_t)i * 4);
        __half2 h0 = __floats2half2_rn(v.x, v.y);
        __half2 h1 = __floats2half2_rn(v.z, v.w);
        uint2 p;
        p.x = *(u32*)&h0; p.y = *(u32*)&h1;
        *(uint2*)(g_xh + (size_t)i * 4) = p;
    }
    if (i < 65536) {                                    // weights
        int mat = i >> 14, e = i & 16383;
        int n = e >> 7, k = e & 127;
        const float* W = (mat == 0) ? Wn0 : (mat == 1) ? Wr0 : (mat == 2) ? Wn1 : Wr1;
        g_wimg[mat][n * 128 + k] = __half_as_ushort(__float2half_rn(W[k * 128 + n]));
    }
    if (i < NN) g_deg[i] = 0;                           // zero degree
}

// ---------------- mean aggregation: fp16 gather -> fp16 out -----------------
__global__ void k_agg(const __half* __restrict__ feat, __half* __restrict__ out) {
    int w    = (blockIdx.x * blockDim.x + threadIdx.x) >> 5;
    int lane = threadIdx.x & 31;
    if (w >= NN) return;
    int beg = g_rowoff[w], end = g_rowoff[w + 1];
    float ax = 0.f, ay = 0.f, az = 0.f, aw = 0.f;
    int e = beg;
    for (; e + 4 <= end; e += 4) {                 // MLP = 4 on the gather
        int s0 = g_csr_src[e],     s1 = g_csr_src[e + 1];
        int s2 = g_csr_src[e + 2], s3 = g_csr_src[e + 3];
        uint2 r0 = *(const uint2*)(feat + (size_t)s0 * DH + lane * 4);
        uint2 r1 = *(const uint2*)(feat + (size_t)s1 * DH + lane * 4);
        uint2 r2 = *(const uint2*)(feat + (size_t)s2 * DH + lane * 4);
        uint2 r3 = *(const uint2*)(feat + (size_t)s3 * DH + lane * 4);
#pragma unroll
        for (int q = 0; q < 4; q++) {
            uint2 r = (q == 0) ? r0 : (q == 1) ? r1 : (q == 2) ? r2 : r3;
            float2 f0 = __half22float2(*(__half2*)&r.x);
            float2 f1 = __half22float2(*(__half2*)&r.y);
            ax += f0.x; ay += f0.y; az += f1.x; aw += f1.y;
        }
    }
    for (; e < end; e++) {
        int s0 = g_csr_src[e];
        uint2 r = *(const uint2*)(feat + (size_t)s0 * DH + lane * 4);
        float2 f0 = __half22float2(*(__half2*)&r.x);
        float2 f1 = __half22float2(*(__half2*)&r.y);
        ax += f0.x; ay += f0.y; az += f1.x; aw += f1.y;
    }
    int deg = end - beg;
    float inv = 1.0f / (float)(deg > 1 ? deg : 1);
    __half2 o0 = __floats2half2_rn(ax * inv, ay * inv);
    __half2 o1 = __floats2half2_rn(az * inv, aw * inv);
    uint2 p;
    p.x = *(u32*)&o0; p.y = *(u32*)&o1;
    *(uint2*)(out + (size_t)w * DH + lane * 4) = p;
}

// ---------------- MMA primitives ---------------------------------------------
__device__ __forceinline__ void ldm_x4(u32& r0, u32& r1, u32& r2, u32& r3, u32 addr) {
    asm volatile("ldmatrix.sync.aligned.m8n8.x4.shared.b16 {%0,%1,%2,%3}, [%4];"
                 : "=r"(r0), "=r"(r1), "=r"(r2), "=r"(r3) : "r"(addr));
}
__device__ __forceinline__ void mma16816(float* c, const u32* a, u32 b0, u32 b1) {
    asm volatile(
        "mma.sync.aligned.m16n8k16.row.col.f32.f16.f16.f32 "
        "{%0,%1,%2,%3},{%4,%5,%6,%7},{%8,%9},{%0,%1,%2,%3};"
        : "+f"(c[0]), "+f"(c[1]), "+f"(c[2]), "+f"(c[3])
        : "r"(a[0]), "r"(a[1]), "r"(a[2]), "r"(a[3]), "r"(b0), "r"(b1));
}

// ---------------- GEMM core: uniform fp16, K=256 in 4 chunks of 64 ----------
// acc += AggH @ Wn + RootH @ Wr   (chunks 0,1 = agg/Wn; 2,3 = root/Wr)
struct GemmSmem {
    u16 As[128 * SB];
    u16 Bs[128 * SB];
};

__device__ __forceinline__ void gemm_core(
    GemmSmem& sm, const __half* __restrict__ AggH, const __half* __restrict__ RootH,
    const u16* __restrict__ Bn, const u16* __restrict__ Br,
    int blockRow, int tid, int lane, int warpR, int warpC,
    float acc[2][8][4])
{
    const u32 a_b = smem_u32(sm.As), b_b = smem_u32(sm.Bs);
    const int arow = tid >> 1, acol = (tid & 1) * 32;
    const int agrow = blockRow + arow;

#pragma unroll
    for (int kc = 0; kc < 4; kc++) {
        const __half* src  = (kc < 2) ? AggH : RootH;
        const u16*    Bimg = (kc < 2) ? Bn   : Br;
        const int koff = (kc & 1) * 64;

        __syncthreads();   // previous chunk fully consumed
        // ---- A fill: 32 halves per thread (4 x uint4) ----
        {
            const __half* rp = src + (size_t)agrow * DH + koff + acol;
            u16* dp = &sm.As[arow * SB + acol];
            if (agrow < NN) {
#pragma unroll
                for (int j = 0; j < 4; j++)
                    *(uint4*)(dp + j * 8) = *(const uint4*)(rp + j * 8);
            } else {
                uint4 z = make_uint4(0, 0, 0, 0);
#pragma unroll
                for (int j = 0; j < 4; j++) *(uint4*)(dp + j * 8) = z;
            }
        }
        // ---- B fill: 32 halves per thread ----
        {
            const u16* rp = Bimg + arow * 128 + koff + acol;
            u16* dp = &sm.Bs[arow * SB + acol];
#pragma unroll
            for (int j = 0; j < 4; j++)
                *(uint4*)(dp + j * 8) = *(const uint4*)(rp + j * 8);
        }
        __syncthreads();

        // ---- compute: 4 k-steps x 16 mma ----
#pragma unroll
        for (int ks = 0; ks < 4; ks++) {
            int k0 = ks * 16;
            u32 afrag[2][4];
#pragma unroll
            for (int mi = 0; mi < 2; mi++) {
                int rowA = warpR + mi * 16 + (lane & 15);
                int colA = k0 + ((lane >> 4) << 3);
                ldm_x4(afrag[mi][0], afrag[mi][1], afrag[mi][2], afrag[mi][3],
                       a_b + (u32)(rowA * SB + colA) * 2);
            }
            u32 bfrag[4][4];
#pragma unroll
            for (int pj = 0; pj < 4; pj++) {
                int nB = warpC + pj * 16 + ((lane >> 4) << 3) + (lane & 7);
                int kB = k0 + (lane & 8);
                ldm_x4(bfrag[pj][0], bfrag[pj][1], bfrag[pj][2], bfrag[pj][3],
                       b_b + (u32)(nB * SB + kB) * 2);
            }
#pragma unroll
            for (int mi = 0; mi < 2; mi++)
#pragma unroll
                for (int nj = 0; nj < 8; nj++) {
                    const u32* bp = bfrag[nj >> 1];
                    u32 b0 = (nj & 1) ? bp[2] : bp[0];
                    u32 b1 = (nj & 1) ? bp[3] : bp[1];
                    mma16816(acc[mi][nj], afrag[mi], b0, b1);
                }
        }
    }
}

// ---------------- GEMM kernel: mid layer (fp16 hidden out) -------------------
__global__ __launch_bounds__(256, 2)
void k_gemm_mid(const __half* __restrict__ AggH, const __half* __restrict__ RootH,
                const u16* __restrict__ Bn, const u16* __restrict__ Br,
                const float* __restrict__ bias, __half* __restrict__ HoutH)
{
    __shared__ GemmSmem sm;
    const int tid = threadIdx.x, wid = tid >> 5, lane = tid & 31;
    const int blockRow = blockIdx.x * 128;
    const int warpR = (wid & 3) * 32, warpC = (wid >> 2) * 64;

    float acc[2][8][4];
#pragma unroll
    for (int i = 0; i < 2; i++)
#pragma unroll
        for (int j = 0; j < 8; j++)
#pragma unroll
            for (int q = 0; q < 4; q++) acc[i][j][q] = 0.f;

    gemm_core(sm, AggH, RootH, Bn, Br, blockRow, tid, lane, warpR, warpC, acc);

    const int g = lane >> 2, tg = lane & 3;
#pragma unroll
    for (int mi = 0; mi < 2; mi++) {
        int row0 = blockRow + warpR + mi * 16 + g;
        int row1 = row0 + 8;
#pragma unroll
        for (int nj = 0; nj < 8; nj++) {
            int col = warpC + nj * 8 + tg * 2;
            float b0v = bias[col], b1v = bias[col + 1];
            if (row0 < NN)
                *(__half2*)(HoutH + (size_t)row0 * DH + col) =
                    __floats2half2_rn(fmaxf(acc[mi][nj][0] + b0v, 0.f),
                                      fmaxf(acc[mi][nj][1] + b1v, 0.f));
            if (row1 < NN)
                *(__half2*)(HoutH + (size_t)row1 * DH + col) =
                    __floats2half2_rn(fmaxf(acc[mi][nj][2] + b0v, 0.f),
                                      fmaxf(acc[mi][nj][3] + b1v, 0.f));
        }
    }
}

// ---------------- GEMM kernel: last layer + fused head -----------------------
__global__ __launch_bounds__(256, 2)
void k_gemm_head(const __half* __restrict__ AggH, const __half* __restrict__ RootH,
                 const u16* __restrict__ Bn, const u16* __restrict__ Br,
                 const float* __restrict__ bias,
                 const float* __restrict__ Wh, const float* __restrict__ bh,
                 float* __restrict__ out)
{
    __shared__ GemmSmem sm;
    __shared__ float HeadPart[2][128];
    const int tid = threadIdx.x, wid = tid >> 5, lane = tid & 31;
    const int blockRow = blockIdx.x * 128;
    const int warpR = (wid & 3) * 32, warpC = (wid >> 2) * 64;

    float acc[2][8][4];
#pragma unroll
    for (int i = 0; i < 2; i++)
#pragma unroll
        for (int j = 0; j < 8; j++)
#pragma unroll
            for (int q = 0; q < 4; q++) acc[i][j][q] = 0.f;

    gemm_core(sm, AggH, RootH, Bn, Br, blockRow, tid, lane, warpR, warpC, acc);

    const int g = lane >> 2, tg = lane & 3;
    float p0[2] = {0.f, 0.f}, p1[2] = {0.f, 0.f};
#pragma unroll
    for (int mi = 0; mi < 2; mi++) {
#pragma unroll
        for (int nj = 0; nj < 8; nj++) {
            int col = warpC + nj * 8 + tg * 2;
            float b0v = bias[col], b1v = bias[col + 1];
            float w0 = Wh[col], w1 = Wh[col + 1];
            p0[mi] += fmaxf(acc[mi][nj][0] + b0v, 0.f) * w0
                    + fmaxf(acc[mi][nj][1] + b1v, 0.f) * w1;
            p1[mi] += fmaxf(acc[mi][nj][2] + b0v, 0.f) * w0
                    + fmaxf(acc[mi][nj][3] + b1v, 0.f) * w1;
        }
    }
#pragma unroll
    for (int off = 1; off <= 2; off <<= 1) {
#pragma unroll
        for (int mi = 0; mi < 2; mi++) {
            p0[mi] += __shfl_xor_sync(0xFFFFFFFFu, p0[mi], off);
            p1[mi] += __shfl_xor_sync(0xFFFFFFFFu, p1[mi], off);
        }
    }
    if (tg == 0) {
#pragma unroll
        for (int mi = 0; mi < 2; mi++) {
            HeadPart[wid >> 2][warpR + mi * 16 + g]     = p0[mi];
            HeadPart[wid >> 2][warpR + mi * 16 + g + 8] = p1[mi];
        }
    }
    __syncthreads();
    if (tid < 128) {
        int r = blockRow + tid;
        if (r < NN) out[r] = HeadPart[0][tid] + HeadPart[1][tid] + bh[0];
    }
}

// ---------------- launch -----------------------------------------------------
extern "C" void kernel_launch(void* const* d_in, const int* in_sizes, int n_in,
                              void* d_out, int out_size) {
    const float* x   = (const float*)d_in[0];
    const int*   ei  = (const int*)  d_in[1];
    const int*   src = ei;
    const int*   dst = ei + NE;
    const float* Wn0 = (const float*)d_in[2];
    const float* Wr0 = (const float*)d_in[3];
    const float* b0  = (const float*)d_in[4];
    const float* Wn1 = (const float*)d_in[5];
    const float* Wr1 = (const float*)d_in[6];
    const float* b1  = (const float*)d_in[7];
    const float* Wh  = (const float*)d_in[8];
    const float* bh  = (const float*)d_in[9];
    float* out = (float*)d_out;

    __half *aggh, *xh, *h1h;
    u16* wimg;
    cudaGetSymbolAddress((void**)&aggh, g_aggh);
    cudaGetSymbolAddress((void**)&xh,   g_xh);
    cudaGetSymbolAddress((void**)&h1h,  g_h1h);
    cudaGetSymbolAddress((void**)&wimg, g_wimg);

    const int NB_N = (NN + 255) / 256;
    const int NB_E = (NE + 255) / 256;
    const int NB_W = (NN * 32 + 255) / 256;
    const int NB_P = (NN * DH / 4 + 255) / 256;

    // fused prep (x->fp16, weights, deg=0)
    k_prep<<<NB_P, 256>>>(x, Wn0, Wr0, Wn1, Wr1);

    // CSR build
    k_count     <<<NB_E, 256>>>(dst);
    k_scan_block<<<NB_N, 256>>>();
    k_scan_top  <<<1,   512>>>(NB_N);
    k_scan_add  <<<NB_N, 256>>>();
    k_scatter   <<<NB_E, 256>>>(src, dst);

    // layer 0
    k_agg     <<<NB_W, 256>>>(xh, aggh);
    k_gemm_mid<<<NTILES, 256>>>(aggh, xh,
        wimg + 0 * 16384, wimg + 1 * 16384, b0, h1h);
    // layer 1 + fused head
    k_agg      <<<NB_W, 256>>>(h1h, aggh);
    k_gemm_head<<<NTILES, 256>>>(aggh, h1h,
        wimg + 2 * 16384, wimg + 3 * 16384, b1, Wh, bh, out);
}